// round 3
// baseline (speedup 1.0000x reference)
#include <cuda_runtime.h>
#include <cuda_bf16.h>
#include <math_constants.h>

#define BATCH 4
#define SEQ 4096
#define DMODEL 1024
#define DHEAD 128
#define MROWS (BATCH*SEQ)   // 16384

// Scratch for projected Q, K, V (device globals: no allocations allowed)
__device__ float g_Q[MROWS*DHEAD];
__device__ float g_K[MROWS*DHEAD];
__device__ float g_V[MROWS*DHEAD];

__device__ __forceinline__ unsigned f2tf32(float x){
    unsigned y; asm("cvt.rna.tf32.f32 %0, %1;" : "=r"(y) : "f"(x)); return y;
}

__device__ __forceinline__ void mma_tf32(float* d,
    unsigned a0, unsigned a1, unsigned a2, unsigned a3,
    unsigned b0, unsigned b1)
{
    asm volatile(
        "mma.sync.aligned.m16n8k8.row.col.f32.tf32.tf32.f32 "
        "{%0,%1,%2,%3}, {%4,%5,%6,%7}, {%8,%9}, {%0,%1,%2,%3};"
        : "+f"(d[0]), "+f"(d[1]), "+f"(d[2]), "+f"(d[3])
        : "r"(a0), "r"(a1), "r"(a2), "r"(a3), "r"(b0), "r"(b1));
}

// ============================================================================
// Projection: Y[16384,128] = X[16384,1024] @ W[128,1024]^T   (tf32 HMMA)
// CTA tile 128x128, K-step 32. 8 warps in 4x2 grid, each warp 32x64.
// ============================================================================
#define PSTR 36   // smem stride (32 + 4): fragment loads bank-conflict-free

__global__ __launch_bounds__(256, 2) void proj_kernel(
    const float* __restrict__ q, const float* __restrict__ k, const float* __restrict__ v,
    const float* __restrict__ wq, const float* __restrict__ wk, const float* __restrict__ wv)
{
    __shared__ unsigned Xs[128*PSTR];
    __shared__ unsigned Ws[128*PSTR];

    const float* X; const float* W; float* Y;
    if (blockIdx.z == 0)      { X = q; W = wq; Y = g_Q; }
    else if (blockIdx.z == 1) { X = k; W = wk; Y = g_K; }
    else                      { X = v; W = wv; Y = g_V; }

    const int row0 = blockIdx.x * 128;
    const int tid  = threadIdx.x;
    const int wid  = tid >> 5;
    const int lane = tid & 31;
    const int g    = lane >> 2;   // groupID
    const int t    = lane & 3;    // threadID in group
    const int wr   = (wid >> 1) * 32;  // warp row base
    const int wc   = (wid & 1) * 64;   // warp col base

    float acc[2][8][4] = {};

    for (int k0 = 0; k0 < DMODEL; k0 += 32) {
        // 128x32 tiles of X and W, float4 loads (8 float4 per row)
        #pragma unroll
        for (int i = 0; i < 4; i++) {
            int e = tid + i * 256;        // float4 index, 0..1023
            int r = e >> 3, c = e & 7;    // row, float4-col
            float4 x = *(const float4*)&X[(size_t)(row0 + r) * DMODEL + k0 + c*4];
            float4 w = *(const float4*)&W[(size_t)r * DMODEL + k0 + c*4];
            uint4 xt = { f2tf32(x.x), f2tf32(x.y), f2tf32(x.z), f2tf32(x.w) };
            uint4 wt = { f2tf32(w.x), f2tf32(w.y), f2tf32(w.z), f2tf32(w.w) };
            *(uint4*)&Xs[r*PSTR + c*4] = xt;
            *(uint4*)&Ws[r*PSTR + c*4] = wt;
        }
        __syncthreads();

        #pragma unroll
        for (int kt = 0; kt < 4; kt++) {
            unsigned a[2][4];
            #pragma unroll
            for (int mt = 0; mt < 2; mt++) {
                int r = wr + mt * 16;
                a[mt][0] = Xs[(r + g    )*PSTR + kt*8 + t];
                a[mt][1] = Xs[(r + g + 8)*PSTR + kt*8 + t];
                a[mt][2] = Xs[(r + g    )*PSTR + kt*8 + t + 4];
                a[mt][3] = Xs[(r + g + 8)*PSTR + kt*8 + t + 4];
            }
            #pragma unroll
            for (int nt = 0; nt < 8; nt++) {
                unsigned b0 = Ws[(wc + nt*8 + g)*PSTR + kt*8 + t];
                unsigned b1 = Ws[(wc + nt*8 + g)*PSTR + kt*8 + t + 4];
                mma_tf32(acc[0][nt], a[0][0], a[0][1], a[0][2], a[0][3], b0, b1);
                mma_tf32(acc[1][nt], a[1][0], a[1][1], a[1][2], a[1][3], b0, b1);
            }
        }
        __syncthreads();
    }

    // Epilogue: C frag (g,2t),(g,2t+1),(g+8,2t),(g+8,2t+1)
    #pragma unroll
    for (int mt = 0; mt < 2; mt++) {
        int r = row0 + wr + mt*16 + g;
        #pragma unroll
        for (int nt = 0; nt < 8; nt++) {
            int c = wc + nt*8 + 2*t;
            float2 v0 = make_float2(acc[mt][nt][0], acc[mt][nt][1]);
            float2 v1 = make_float2(acc[mt][nt][2], acc[mt][nt][3]);
            *(float2*)&Y[(size_t)r * DHEAD + c]       = v0;
            *(float2*)&Y[(size_t)(r + 8) * DHEAD + c] = v1;
        }
    }
}

// ============================================================================
// Flash attention, causal. CTA: 128 query rows, 64-key tiles, D=128.
// 8 warps; warp w owns query rows [16w, 16w+16) end-to-end (S, softmax, O).
// exp2-domain softmax: Q pre-scaled by log2(e)/sqrt(128).
// ============================================================================
#define QSTR 132
#define KSTR 132
#define VSTR 136
#define PSTRD 68
#define QS_SZ (128*QSTR)
#define KS_SZ (64*KSTR)
#define VS_SZ (64*VSTR)
#define PS_SZ (128*PSTRD)
#define FLASH_SMEM ((QS_SZ + KS_SZ + VS_SZ + PS_SZ) * 4)   // 171008 B

__global__ __launch_bounds__(256, 1) void flash_kernel(float* __restrict__ out)
{
    extern __shared__ unsigned sm[];
    unsigned* Qs = sm;
    unsigned* Ks = Qs + QS_SZ;
    unsigned* Vs = Ks + KS_SZ;
    unsigned* Ps = Vs + VS_SZ;

    const int b     = blockIdx.y;
    const int ib    = blockIdx.x;
    const int qrow0 = ib * 128;
    const float* Q = g_Q + (size_t)b * SEQ * DHEAD;
    const float* K = g_K + (size_t)b * SEQ * DHEAD;
    const float* V = g_V + (size_t)b * SEQ * DHEAD;
    float* O       = out + (size_t)b * SEQ * DHEAD;

    const int tid  = threadIdx.x;
    const int wid  = tid >> 5;
    const int lane = tid & 31;
    const int g    = lane >> 2;
    const int t    = lane & 3;
    const int rA   = wid * 16 + g;          // local row (and rA+8)

    const float QSCALE = 1.4426950408889634f * 0.08838834764831845f; // log2e/sqrt(128)

    // Q tile: 128x128, float4 loads (32 float4 per row)
    {
        const float4* Q4 = (const float4*)(Q + (size_t)qrow0 * DHEAD);
        #pragma unroll
        for (int i = 0; i < 16; i++) {
            int e = tid + i * 256;        // float4 index, 0..4095
            int r = e >> 5, c = e & 31;
            float4 x = Q4[e];
            uint4 y = { f2tf32(x.x * QSCALE), f2tf32(x.y * QSCALE),
                        f2tf32(x.z * QSCALE), f2tf32(x.w * QSCALE) };
            *(uint4*)&Qs[r*QSTR + c*4] = y;
        }
    }

    float o[16][4] = {};
    float mA = -CUDART_INF_F, mB = -CUDART_INF_F;
    float lA = 0.f, lB = 0.f;

    const int jmax = 2 * ib + 2;
    for (int j = 0; j < jmax; j++) {
        __syncthreads();   // previous tile's V reads done (also orders Q load on j=0)
        {
            const float4* K4 = (const float4*)(K + (size_t)j * 64 * DHEAD);
            const float4* V4 = (const float4*)(V + (size_t)j * 64 * DHEAD);
            #pragma unroll
            for (int i = 0; i < 8; i++) {
                int e = tid + i * 256;    // float4 index, 0..2047
                int r = e >> 5, c = e & 31;
                float4 kx = K4[e];
                float4 vx = V4[e];
                uint4 kt4 = { f2tf32(kx.x), f2tf32(kx.y), f2tf32(kx.z), f2tf32(kx.w) };
                uint4 vt4 = { f2tf32(vx.x), f2tf32(vx.y), f2tf32(vx.z), f2tf32(vx.w) };
                *(uint4*)&Ks[r*KSTR + c*4] = kt4;
                *(uint4*)&Vs[r*VSTR + c*4] = vt4;
            }
        }
        __syncthreads();

        // ---- S = Q @ K^T : per-warp 16x64 ----
        float s[8][4] = {};
        #pragma unroll
        for (int kt = 0; kt < 16; kt++) {
            unsigned a0 = Qs[(rA    )*QSTR + kt*8 + t];
            unsigned a1 = Qs[(rA + 8)*QSTR + kt*8 + t];
            unsigned a2 = Qs[(rA    )*QSTR + kt*8 + t + 4];
            unsigned a3 = Qs[(rA + 8)*QSTR + kt*8 + t + 4];
            #pragma unroll
            for (int nt = 0; nt < 8; nt++) {
                unsigned b0 = Ks[(nt*8 + g)*KSTR + kt*8 + t];
                unsigned b1 = Ks[(nt*8 + g)*KSTR + kt*8 + t + 4];
                mma_tf32(s[nt], a0, a1, a2, a3, b0, b1);
            }
        }

        // ---- causal mask (only tiles overlapping the diagonal band) ----
        if (j >= 2 * ib) {
            int rowA = qrow0 + rA, rowB = rowA + 8;
            #pragma unroll
            for (int nt = 0; nt < 8; nt++) {
                int c0 = j*64 + nt*8 + 2*t;
                if (c0     > rowA) s[nt][0] = -CUDART_INF_F;
                if (c0 + 1 > rowA) s[nt][1] = -CUDART_INF_F;
                if (c0     > rowB) s[nt][2] = -CUDART_INF_F;
                if (c0 + 1 > rowB) s[nt][3] = -CUDART_INF_F;
            }
        }

        // ---- online softmax (per-row, 2 rows per thread) ----
        float tmA = -CUDART_INF_F, tmB = -CUDART_INF_F;
        #pragma unroll
        for (int nt = 0; nt < 8; nt++) {
            tmA = fmaxf(tmA, fmaxf(s[nt][0], s[nt][1]));
            tmB = fmaxf(tmB, fmaxf(s[nt][2], s[nt][3]));
        }
        tmA = fmaxf(tmA, __shfl_xor_sync(0xffffffffu, tmA, 1));
        tmA = fmaxf(tmA, __shfl_xor_sync(0xffffffffu, tmA, 2));
        tmB = fmaxf(tmB, __shfl_xor_sync(0xffffffffu, tmB, 1));
        tmB = fmaxf(tmB, __shfl_xor_sync(0xffffffffu, tmB, 2));

        float mnA = fmaxf(mA, tmA), mnB = fmaxf(mB, tmB);
        float scA = exp2f(mA - mnA), scB = exp2f(mB - mnB);
        mA = mnA; mB = mnB;

        float rsA = 0.f, rsB = 0.f;
        #pragma unroll
        for (int nt = 0; nt < 8; nt++) {
            float p0 = exp2f(s[nt][0] - mnA);
            float p1 = exp2f(s[nt][1] - mnA);
            float p2 = exp2f(s[nt][2] - mnB);
            float p3 = exp2f(s[nt][3] - mnB);
            rsA += p0 + p1;  rsB += p2 + p3;
            int c = nt*8 + 2*t;
            Ps[(rA    )*PSTRD + c]     = f2tf32(p0);
            Ps[(rA    )*PSTRD + c + 1] = f2tf32(p1);
            Ps[(rA + 8)*PSTRD + c]     = f2tf32(p2);
            Ps[(rA + 8)*PSTRD + c + 1] = f2tf32(p3);
        }
        lA = lA * scA + rsA;
        lB = lB * scB + rsB;

        #pragma unroll
        for (int nt = 0; nt < 16; nt++) {
            o[nt][0] *= scA; o[nt][1] *= scA;
            o[nt][2] *= scB; o[nt][3] *= scB;
        }

        __syncwarp();  // P tile is warp-private; order writes before fragment reads

        // ---- O += P @ V : per-warp 16x128, K-dim 64 ----
        #pragma unroll
        for (int kt = 0; kt < 8; kt++) {
            unsigned a0 = Ps[(rA    )*PSTRD + kt*8 + t];
            unsigned a1 = Ps[(rA + 8)*PSTRD + kt*8 + t];
            unsigned a2 = Ps[(rA    )*PSTRD + kt*8 + t + 4];
            unsigned a3 = Ps[(rA + 8)*PSTRD + kt*8 + t + 4];
            #pragma unroll
            for (int nt = 0; nt < 16; nt++) {
                unsigned b0 = Vs[(kt*8 + t    )*VSTR + nt*8 + g];
                unsigned b1 = Vs[(kt*8 + t + 4)*VSTR + nt*8 + g];
                mma_tf32(o[nt], a0, a1, a2, a3, b0, b1);
            }
        }
    }

    // ---- epilogue: normalize and store ----
    lA += __shfl_xor_sync(0xffffffffu, lA, 1);
    lA += __shfl_xor_sync(0xffffffffu, lA, 2);
    lB += __shfl_xor_sync(0xffffffffu, lB, 1);
    lB += __shfl_xor_sync(0xffffffffu, lB, 2);
    float iA = 1.f / lA, iB = 1.f / lB;

    int growA = qrow0 + rA;
    #pragma unroll
    for (int nt = 0; nt < 16; nt++) {
        int c = nt*8 + 2*t;
        float2 v0 = make_float2(o[nt][0] * iA, o[nt][1] * iA);
        float2 v1 = make_float2(o[nt][2] * iB, o[nt][3] * iB);
        *(float2*)&O[(size_t)growA * DHEAD + c]       = v0;
        *(float2*)&O[(size_t)(growA + 8) * DHEAD + c] = v1;
    }
}

// ============================================================================
extern "C" void kernel_launch(void* const* d_in, const int* in_sizes, int n_in,
                              void* d_out, int out_size)
{
    const float* q  = (const float*)d_in[0];
    const float* k  = (const float*)d_in[1];
    const float* v  = (const float*)d_in[2];
    const float* wq = (const float*)d_in[3];
    const float* wk = (const float*)d_in[4];
    const float* wv = (const float*)d_in[5];
    float* out = (float*)d_out;

    cudaFuncSetAttribute(flash_kernel,
                         cudaFuncAttributeMaxDynamicSharedMemorySize, FLASH_SMEM);

    proj_kernel<<<dim3(MROWS/128, 1, 3), 256>>>(q, k, v, wq, wk, wv);
    flash_kernel<<<dim3(SEQ/128, BATCH), 256, FLASH_SMEM>>>(out);
}

// round 6
// speedup vs baseline: 1.3223x; 1.3223x over previous
#include <cuda_runtime.h>
#include <cuda_bf16.h>
#include <math_constants.h>

#define BATCH 4
#define SEQ 4096
#define DMODEL 1024
#define DHEAD 128
#define MROWS (BATCH*SEQ)   // 16384

#define CHUNK 16            // max KV tiles (of 64 keys) per work unit
#define NUNITS 320          // 4 batches * sum_ib ceil((2ib+2)/16) = 4*80
#define NSLOTS 512          // (b*32+ib)*4 + c, c < 4

// Scratch (device globals: no allocations allowed)
__device__ float g_Q[MROWS*DHEAD];
__device__ float g_K[MROWS*DHEAD];
__device__ float g_V[MROWS*DHEAD];
__device__ float g_pO[NSLOTS*128*DHEAD];   // un-normalized partial O per slot
__device__ float g_pm[NSLOTS*128];         // per-row running max (exp2 domain)
__device__ float g_pl[NSLOTS*128];         // per-row partial denom
__device__ int   g_ctr;                    // persistent-kernel work counter

__device__ __forceinline__ unsigned f2tf32(float x){
    unsigned y; asm("cvt.rna.tf32.f32 %0, %1;" : "=r"(y) : "f"(x)); return y;
}

__device__ __forceinline__ void mma_tf32(float* d,
    unsigned a0, unsigned a1, unsigned a2, unsigned a3,
    unsigned b0, unsigned b1)
{
    asm volatile(
        "mma.sync.aligned.m16n8k8.row.col.f32.tf32.tf32.f32 "
        "{%0,%1,%2,%3}, {%4,%5,%6,%7}, {%8,%9}, {%0,%1,%2,%3};"
        : "+f"(d[0]), "+f"(d[1]), "+f"(d[2]), "+f"(d[3])
        : "r"(a0), "r"(a1), "r"(a2), "r"(a3), "r"(b0), "r"(b1));
}

// ============================================================================
// Projection: Y[16384,128] = X[16384,1024] @ W[128,1024]^T   (tf32 HMMA)
// ============================================================================
#define PSTR 36

__global__ __launch_bounds__(256, 2) void proj_kernel(
    const float* __restrict__ q, const float* __restrict__ k, const float* __restrict__ v,
    const float* __restrict__ wq, const float* __restrict__ wk, const float* __restrict__ wv)
{
    __shared__ unsigned Xs[128*PSTR];
    __shared__ unsigned Ws[128*PSTR];

    const float* X; const float* W; float* Y;
    if (blockIdx.z == 0)      { X = q; W = wq; Y = g_Q; }
    else if (blockIdx.z == 1) { X = k; W = wk; Y = g_K; }
    else                      { X = v; W = wv; Y = g_V; }

    const int row0 = blockIdx.x * 128;
    const int tid  = threadIdx.x;
    const int wid  = tid >> 5;
    const int lane = tid & 31;
    const int g    = lane >> 2;
    const int t    = lane & 3;
    const int wr   = (wid >> 1) * 32;
    const int wc   = (wid & 1) * 64;

    float acc[2][8][4] = {};

    for (int k0 = 0; k0 < DMODEL; k0 += 32) {
        #pragma unroll
        for (int i = 0; i < 4; i++) {
            int e = tid + i * 256;
            int r = e >> 3, c = e & 7;
            float4 x = *(const float4*)&X[(size_t)(row0 + r) * DMODEL + k0 + c*4];
            float4 w = *(const float4*)&W[(size_t)r * DMODEL + k0 + c*4];
            uint4 xt = { f2tf32(x.x), f2tf32(x.y), f2tf32(x.z), f2tf32(x.w) };
            uint4 wt = { f2tf32(w.x), f2tf32(w.y), f2tf32(w.z), f2tf32(w.w) };
            *(uint4*)&Xs[r*PSTR + c*4] = xt;
            *(uint4*)&Ws[r*PSTR + c*4] = wt;
        }
        __syncthreads();

        #pragma unroll
        for (int kt = 0; kt < 4; kt++) {
            unsigned a[2][4];
            #pragma unroll
            for (int mt = 0; mt < 2; mt++) {
                int r = wr + mt * 16;
                a[mt][0] = Xs[(r + g    )*PSTR + kt*8 + t];
                a[mt][1] = Xs[(r + g + 8)*PSTR + kt*8 + t];
                a[mt][2] = Xs[(r + g    )*PSTR + kt*8 + t + 4];
                a[mt][3] = Xs[(r + g + 8)*PSTR + kt*8 + t + 4];
            }
            #pragma unroll
            for (int nt = 0; nt < 8; nt++) {
                unsigned b0 = Ws[(wc + nt*8 + g)*PSTR + kt*8 + t];
                unsigned b1 = Ws[(wc + nt*8 + g)*PSTR + kt*8 + t + 4];
                mma_tf32(acc[0][nt], a[0][0], a[0][1], a[0][2], a[0][3], b0, b1);
                mma_tf32(acc[1][nt], a[1][0], a[1][1], a[1][2], a[1][3], b0, b1);
            }
        }
        __syncthreads();
    }

    #pragma unroll
    for (int mt = 0; mt < 2; mt++) {
        int r = row0 + wr + mt*16 + g;
        #pragma unroll
        for (int nt = 0; nt < 8; nt++) {
            int c = wc + nt*8 + 2*t;
            float2 v0 = make_float2(acc[mt][nt][0], acc[mt][nt][1]);
            float2 v1 = make_float2(acc[mt][nt][2], acc[mt][nt][3]);
            *(float2*)&Y[(size_t)r * DHEAD + c]       = v0;
            *(float2*)&Y[(size_t)(r + 8) * DHEAD + c] = v1;
        }
    }
}

// ============================================================================
// Split-KV flash attention, causal. Persistent CTAs pull work units from an
// atomic counter (big-units-first order = LPT scheduling).
// Unit = (batch, qblock of 128 rows, KV chunk of <=16 tiles of 64 keys).
// Chunking guarantees: non-last chunks are fully unmasked; last chunk has >=2
// tiles so every row sees at least one valid key before the masked band.
// ============================================================================
#define QSTR 132
#define KSTR 132
#define VSTR 136
#define PSTRD 68
#define QS_SZ (128*QSTR)
#define KS_SZ (64*KSTR)
#define VS_SZ (64*VSTR)
#define PS_SZ (128*PSTRD)
#define FLASH_SMEM ((QS_SZ + KS_SZ + VS_SZ + PS_SZ) * 4)   // 171008 B

__device__ __forceinline__ void decode_unit(int u, int& b, int& ib,
                                            int& j0, int& j1, int& slot)
{
    b = u & 3;
    int v = u >> 2;              // 0..79, descending-ib order (big units first)
    int acc = 0, ibb = 0, n = 1;
    #pragma unroll 1
    for (int i = 31; i >= 0; --i) {
        int jm = 2*i + 2;
        int ni = (jm + CHUNK - 1) / CHUNK;
        if (v < acc + ni) { ibb = i; n = ni; break; }
        acc += ni;
    }
    int c    = v - acc;
    int jmax = 2*ibb + 2;
    int len  = (jmax + n - 1) / n;
    j0 = c * len;
    j1 = min(jmax, j0 + len);
    ib = ibb;
    slot = ((b*32 + ibb) << 2) + c;
}

__global__ __launch_bounds__(256, 1) void flash_kernel()
{
    extern __shared__ unsigned sm[];
    unsigned* Qs = sm;
    unsigned* Ks = Qs + QS_SZ;
    unsigned* Vs = Ks + KS_SZ;
    unsigned* Ps = Vs + VS_SZ;
    __shared__ int s_unit;

    const int tid  = threadIdx.x;
    const int wid  = tid >> 5;
    const int lane = tid & 31;
    const int g    = lane >> 2;
    const int t    = lane & 3;
    const int rA   = wid * 16 + g;   // local row (and rA+8)

    const float QSCALE = 1.4426950408889634f * 0.08838834764831845f; // log2e/sqrt(128)

    for (;;) {
        if (tid == 0) s_unit = atomicAdd(&g_ctr, 1);
        __syncthreads();             // broadcast; also fences prior unit's smem reads
        int u = s_unit;
        if (u >= NUNITS) break;

        int b, ib, j0, j1, slot;
        decode_unit(u, b, ib, j0, j1, slot);
        const int qrow0 = ib * 128;
        const float* Q = g_Q + (size_t)b * SEQ * DHEAD;
        const float* K = g_K + (size_t)b * SEQ * DHEAD;
        const float* V = g_V + (size_t)b * SEQ * DHEAD;

        // Q tile: 128x128, float4 loads
        {
            const float4* Q4 = (const float4*)(Q + (size_t)qrow0 * DHEAD);
            #pragma unroll
            for (int i = 0; i < 16; i++) {
                int e = tid + i * 256;
                int r = e >> 5, c = e & 31;
                float4 x = Q4[e];
                uint4 y = { f2tf32(x.x * QSCALE), f2tf32(x.y * QSCALE),
                            f2tf32(x.z * QSCALE), f2tf32(x.w * QSCALE) };
                *(uint4*)&Qs[r*QSTR + c*4] = y;
            }
        }

        float o[16][4] = {};
        float mA = -CUDART_INF_F, mB = -CUDART_INF_F;
        float lA = 0.f, lB = 0.f;

        for (int j = j0; j < j1; j++) {
            __syncthreads();   // prev tile's V reads done (also orders Q store on first)
            {
                const float4* K4 = (const float4*)(K + (size_t)j * 64 * DHEAD);
                const float4* V4 = (const float4*)(V + (size_t)j * 64 * DHEAD);
                #pragma unroll
                for (int i = 0; i < 8; i++) {
                    int e = tid + i * 256;
                    int r = e >> 5, c = e & 31;
                    float4 kx = K4[e];
                    float4 vx = V4[e];
                    uint4 kt4 = { f2tf32(kx.x), f2tf32(kx.y), f2tf32(kx.z), f2tf32(kx.w) };
                    uint4 vt4 = { f2tf32(vx.x), f2tf32(vx.y), f2tf32(vx.z), f2tf32(vx.w) };
                    *(uint4*)&Ks[r*KSTR + c*4] = kt4;
                    *(uint4*)&Vs[r*VSTR + c*4] = vt4;
                }
            }
            __syncthreads();

            // ---- S = Q @ K^T : per-warp 16x64 ----
            float s[8][4] = {};
            #pragma unroll
            for (int kt = 0; kt < 16; kt++) {
                unsigned a0 = Qs[(rA    )*QSTR + kt*8 + t];
                unsigned a1 = Qs[(rA + 8)*QSTR + kt*8 + t];
                unsigned a2 = Qs[(rA    )*QSTR + kt*8 + t + 4];
                unsigned a3 = Qs[(rA + 8)*QSTR + kt*8 + t + 4];
                #pragma unroll
                for (int nt = 0; nt < 8; nt++) {
                    unsigned b0 = Ks[(nt*8 + g)*KSTR + kt*8 + t];
                    unsigned b1 = Ks[(nt*8 + g)*KSTR + kt*8 + t + 4];
                    mma_tf32(s[nt], a0, a1, a2, a3, b0, b1);
                }
            }

            // ---- causal mask (only in the diagonal band tiles) ----
            if (j >= 2 * ib) {
                int rowA = qrow0 + rA, rowB = rowA + 8;
                #pragma unroll
                for (int nt = 0; nt < 8; nt++) {
                    int c0 = j*64 + nt*8 + 2*t;
                    if (c0     > rowA) s[nt][0] = -CUDART_INF_F;
                    if (c0 + 1 > rowA) s[nt][1] = -CUDART_INF_F;
                    if (c0     > rowB) s[nt][2] = -CUDART_INF_F;
                    if (c0 + 1 > rowB) s[nt][3] = -CUDART_INF_F;
                }
            }

            // ---- online softmax ----
            float tmA = -CUDART_INF_F, tmB = -CUDART_INF_F;
            #pragma unroll
            for (int nt = 0; nt < 8; nt++) {
                tmA = fmaxf(tmA, fmaxf(s[nt][0], s[nt][1]));
                tmB = fmaxf(tmB, fmaxf(s[nt][2], s[nt][3]));
            }
            tmA = fmaxf(tmA, __shfl_xor_sync(0xffffffffu, tmA, 1));
            tmA = fmaxf(tmA, __shfl_xor_sync(0xffffffffu, tmA, 2));
            tmB = fmaxf(tmB, __shfl_xor_sync(0xffffffffu, tmB, 1));
            tmB = fmaxf(tmB, __shfl_xor_sync(0xffffffffu, tmB, 2));

            float mnA = fmaxf(mA, tmA), mnB = fmaxf(mB, tmB);
            float scA = exp2f(mA - mnA), scB = exp2f(mB - mnB);
            mA = mnA; mB = mnB;

            float rsA = 0.f, rsB = 0.f;
            #pragma unroll
            for (int nt = 0; nt < 8; nt++) {
                float p0 = exp2f(s[nt][0] - mnA);
                float p1 = exp2f(s[nt][1] - mnA);
                float p2 = exp2f(s[nt][2] - mnB);
                float p3 = exp2f(s[nt][3] - mnB);
                rsA += p0 + p1;  rsB += p2 + p3;
                int c = nt*8 + 2*t;
                Ps[(rA    )*PSTRD + c]     = f2tf32(p0);
                Ps[(rA    )*PSTRD + c + 1] = f2tf32(p1);
                Ps[(rA + 8)*PSTRD + c]     = f2tf32(p2);
                Ps[(rA + 8)*PSTRD + c + 1] = f2tf32(p3);
            }
            lA = lA * scA + rsA;
            lB = lB * scB + rsB;

            #pragma unroll
            for (int nt = 0; nt < 16; nt++) {
                o[nt][0] *= scA; o[nt][1] *= scA;
                o[nt][2] *= scB; o[nt][3] *= scB;
            }

            __syncwarp();  // P is warp-private

            // ---- O += P @ V : per-warp 16x128, K-dim 64 ----
            #pragma unroll
            for (int kt = 0; kt < 8; kt++) {
                unsigned a0 = Ps[(rA    )*PSTRD + kt*8 + t];
                unsigned a1 = Ps[(rA + 8)*PSTRD + kt*8 + t];
                unsigned a2 = Ps[(rA    )*PSTRD + kt*8 + t + 4];
                unsigned a3 = Ps[(rA + 8)*PSTRD + kt*8 + t + 4];
                #pragma unroll
                for (int nt = 0; nt < 16; nt++) {
                    unsigned b0 = Vs[(kt*8 + t    )*VSTR + nt*8 + g];
                    unsigned b1 = Vs[(kt*8 + t + 4)*VSTR + nt*8 + g];
                    mma_tf32(o[nt], a0, a1, a2, a3, b0, b1);
                }
            }
        }

        // ---- write un-normalized partial (O, m, l) ----
        lA += __shfl_xor_sync(0xffffffffu, lA, 1);
        lA += __shfl_xor_sync(0xffffffffu, lA, 2);
        lB += __shfl_xor_sync(0xffffffffu, lB, 1);
        lB += __shfl_xor_sync(0xffffffffu, lB, 2);

        float* PO = g_pO + (size_t)slot * 128 * DHEAD;
        #pragma unroll
        for (int nt = 0; nt < 16; nt++) {
            int c = nt*8 + 2*t;
            float2 v0 = make_float2(o[nt][0], o[nt][1]);
            float2 v1 = make_float2(o[nt][2], o[nt][3]);
            *(float2*)&PO[(size_t)rA * DHEAD + c]       = v0;
            *(float2*)&PO[(size_t)(rA + 8) * DHEAD + c] = v1;
        }
        if (t == 0) {
            g_pm[slot*128 + rA]     = mA;
            g_pm[slot*128 + rA + 8] = mB;
            g_pl[slot*128 + rA]     = lA;
            g_pl[slot*128 + rA + 8] = lB;
        }
    }
}

// ============================================================================
// Combine partials: out = (sum_c 2^(m_c-Mg) O_c) / (sum_c 2^(m_c-Mg) l_c)
// One CTA per (batch, qblock). Also resets the work counter for next replay.
// ============================================================================
__global__ __launch_bounds__(256) void combine_kernel(float* __restrict__ out)
{
    if (blockIdx.x == 0 && threadIdx.x == 0) g_ctr = 0;  // flash already done

    const int b  = blockIdx.x >> 5;
    const int ib = blockIdx.x & 31;
    const int jmax = 2*ib + 2;
    const int n    = (jmax + CHUNK - 1) / CHUNK;
    const int base = (b*32 + ib) << 2;
    const int tid  = threadIdx.x;

    __shared__ float w[4][128];
    __shared__ float invL[128];

    if (tid < 128) {
        float mv[4];
        float Mg = -CUDART_INF_F;
        for (int c = 0; c < n; c++) {
            mv[c] = g_pm[(base + c)*128 + tid];
            Mg = fmaxf(Mg, mv[c]);
        }
        float L = 0.f;
        for (int c = 0; c < n; c++) {
            float wc = exp2f(mv[c] - Mg);
            w[c][tid] = wc;
            L += wc * g_pl[(base + c)*128 + tid];
        }
        invL[tid] = 1.f / L;
    }
    __syncthreads();

    float* O = out + ((size_t)b * SEQ + ib * 128) * DHEAD;
    for (int e = tid; e < 128 * 32; e += 256) {     // float4 granularity
        int r  = e >> 5;
        int c4 = (e & 31) * 4;
        float4 acc = make_float4(0.f, 0.f, 0.f, 0.f);
        for (int c = 0; c < n; c++) {
            const float4 p = *(const float4*)&g_pO[((size_t)(base + c) * 128 + r) * DHEAD + c4];
            float wc = w[c][r];
            acc.x += wc * p.x; acc.y += wc * p.y;
            acc.z += wc * p.z; acc.w += wc * p.w;
        }
        float il = invL[r];
        acc.x *= il; acc.y *= il; acc.z *= il; acc.w *= il;
        *(float4*)&O[(size_t)r * DHEAD + c4] = acc;
    }
}

// ============================================================================
extern "C" void kernel_launch(void* const* d_in, const int* in_sizes, int n_in,
                              void* d_out, int out_size)
{
    const float* q  = (const float*)d_in[0];
    const float* k  = (const float*)d_in[1];
    const float* v  = (const float*)d_in[2];
    const float* wq = (const float*)d_in[3];
    const float* wk = (const float*)d_in[4];
    const float* wv = (const float*)d_in[5];
    float* out = (float*)d_out;

    cudaFuncSetAttribute(flash_kernel,
                         cudaFuncAttributeMaxDynamicSharedMemorySize, FLASH_SMEM);

    proj_kernel<<<dim3(MROWS/128, 1, 3), 256>>>(q, k, v, wq, wk, wv);
    flash_kernel<<<148, 256, FLASH_SMEM>>>();
    combine_kernel<<<BATCH*32, 256>>>(out);
}